// round 1
// baseline (speedup 1.0000x reference)
#include <cuda_runtime.h>
#include <math.h>

// Problem constants (fixed shapes from reference)
#define NN    50000
#define EE    800000
#define ET    (EE + NN)          // edges + self loops
#define IND   256
#define HID   32
#define HEADS 4
#define HH    (HEADS * HID)      // 128
#define SLOPE 0.2f

// ---------------- scratch (device globals; no allocations) ----------------
__device__ float d_h1 [NN * HH];
__device__ float d_as1[NN * HEADS];
__device__ float d_ad1[NN * HEADS];
__device__ float d_m1 [NN * HEADS];
__device__ float d_den1[NN * HEADS];
__device__ float d_e1 [ET * HEADS];
__device__ float d_out1[NN * HH];

__device__ float d_h2 [NN * HID];
__device__ float d_as2[NN];
__device__ float d_ad2[NN];
__device__ float d_m2 [NN];
__device__ float d_den2[NN];
__device__ float d_e2 [ET];
__device__ float d_out2[NN * HID];

// ---------------- helpers ----------------
__device__ __forceinline__ void atomicMaxF(float* addr, float v) {
    if (v >= 0.0f) atomicMax((int*)addr, __float_as_int(v));
    else           atomicMin((unsigned int*)addr, __float_as_uint(v));
}

__device__ __forceinline__ void edge_sd(const int* __restrict__ ei, int id, int& s, int& d) {
    if (id < EE) { s = ei[id]; d = ei[EE + id]; }
    else         { s = id - EE; d = id - EE; }
}

__device__ __forceinline__ float lrelu(float v) { return v > 0.0f ? v : SLOPE * v; }
__device__ __forceinline__ float eluf (float v) { return v > 0.0f ? v : __expf(v) - 1.0f; }

// ---------------- init kernels ----------------
__global__ void k_init1() {
    int i = blockIdx.x * blockDim.x + threadIdx.x;
    int stride = gridDim.x * blockDim.x;
    for (int t = i; t < NN * HEADS; t += stride) { d_m1[t] = -3.4e38f; d_den1[t] = 0.0f; }
    for (int t = i; t < NN * HH; t += stride)    d_out1[t] = 0.0f;
}
__global__ void k_init2() {
    int i = blockIdx.x * blockDim.x + threadIdx.x;
    int stride = gridDim.x * blockDim.x;
    for (int t = i; t < NN; t += stride) { d_m2[t] = -3.4e38f; d_den2[t] = 0.0f; }
    for (int t = i; t < NN * HID; t += stride)   d_out2[t] = 0.0f;
}

// ---------------- layer 1: GEMM + attention scalars ----------------
// 8 node-rows per block, 128 threads (thread j = out column j)
__global__ void k_gemm1(const float* __restrict__ x, const float* __restrict__ W,
                        const float* __restrict__ att_s, const float* __restrict__ att_d) {
    __shared__ float xs[8 * IND];
    int n0 = blockIdx.x * 8;
    int j  = threadIdx.x;

    const float4* x4  = (const float4*)(x + (size_t)n0 * IND);
    float4*       xs4 = (float4*)xs;
#pragma unroll
    for (int t = 0; t < 4; t++) xs4[j + t * 128] = x4[j + t * 128];
    __syncthreads();

    float a[8];
#pragma unroll
    for (int r = 0; r < 8; r++) a[r] = 0.0f;

#pragma unroll 4
    for (int k = 0; k < IND; k++) {
        float w = W[k * HH + j];
#pragma unroll
        for (int r = 0; r < 8; r++) a[r] += xs[r * IND + k] * w;
    }

    int lane = j & 31, head = j >> 5;
    float es = att_s[head * HID + lane];
    float ed = att_d[head * HID + lane];

#pragma unroll
    for (int r = 0; r < 8; r++) {
        int n = n0 + r;
        if (n < NN) d_h1[(size_t)n * HH + j] = a[r];
        float s = a[r] * es, t = a[r] * ed;
#pragma unroll
        for (int o = 16; o; o >>= 1) {
            s += __shfl_xor_sync(0xffffffffu, s, o);
            t += __shfl_xor_sync(0xffffffffu, t, o);
        }
        if (lane == 0 && n < NN) { d_as1[n * HEADS + head] = s; d_ad1[n * HEADS + head] = t; }
    }
}

// ---------------- layer 1: edge passes ----------------
__global__ void k_emax1(const int* __restrict__ ei) {
    int id = blockIdx.x * blockDim.x + threadIdx.x;
    if (id >= ET) return;
    int s, d; edge_sd(ei, id, s, d);
    float4 sa = *(const float4*)&d_as1[s * 4];
    float4 da = *(const float4*)&d_ad1[d * 4];
    float v0 = lrelu(sa.x + da.x);
    float v1 = lrelu(sa.y + da.y);
    float v2 = lrelu(sa.z + da.z);
    float v3 = lrelu(sa.w + da.w);
    *(float4*)&d_e1[(size_t)id * 4] = make_float4(v0, v1, v2, v3);
    atomicMaxF(&d_m1[d * 4 + 0], v0);
    atomicMaxF(&d_m1[d * 4 + 1], v1);
    atomicMaxF(&d_m1[d * 4 + 2], v2);
    atomicMaxF(&d_m1[d * 4 + 3], v3);
}

__global__ void k_eexp1(const int* __restrict__ ei) {
    int id = blockIdx.x * blockDim.x + threadIdx.x;
    if (id >= ET) return;
    int s, d; edge_sd(ei, id, s, d);
    (void)s;
    float4 ev = *(const float4*)&d_e1[(size_t)id * 4];
    float4 mv = *(const float4*)&d_m1[d * 4];
    float p0 = __expf(ev.x - mv.x);
    float p1 = __expf(ev.y - mv.y);
    float p2 = __expf(ev.z - mv.z);
    float p3 = __expf(ev.w - mv.w);
    *(float4*)&d_e1[(size_t)id * 4] = make_float4(p0, p1, p2, p3);
    atomicAdd(&d_den1[d * 4 + 0], p0);
    atomicAdd(&d_den1[d * 4 + 1], p1);
    atomicAdd(&d_den1[d * 4 + 2], p2);
    atomicAdd(&d_den1[d * 4 + 3], p3);
}

// warp per edge; lane handles 4 contiguous columns (one head per 8 lanes)
__global__ void k_eagg1(const int* __restrict__ ei) {
    int gid  = blockIdx.x * blockDim.x + threadIdx.x;
    int w    = gid >> 5;
    if (w >= ET) return;
    int lane = gid & 31;
    int s, d; edge_sd(ei, w, s, d);
    int h = lane >> 3;
    float alpha = d_e1[(size_t)w * 4 + h] / d_den1[d * 4 + h];
    float4 hv = *(const float4*)&d_h1[(size_t)s * HH + lane * 4];
    float* o = &d_out1[(size_t)d * HH + lane * 4];
    atomicAdd(o + 0, alpha * hv.x);
    atomicAdd(o + 1, alpha * hv.y);
    atomicAdd(o + 2, alpha * hv.z);
    atomicAdd(o + 3, alpha * hv.w);
}

__global__ void k_fin1(const float* __restrict__ b1) {
    int i = blockIdx.x * blockDim.x + threadIdx.x;
    int stride = gridDim.x * blockDim.x;
    for (int t = i; t < NN * HH; t += stride) {
        float v = d_out1[t] + b1[t & (HH - 1)];
        d_out1[t] = eluf(v);
    }
}

// ---------------- layer 2: GEMM + attention scalars ----------------
// 8 nodes per block, 256 threads; warp w = node n0+w, lane = out column
__global__ void k_gemm2(const float* __restrict__ W2,
                        const float* __restrict__ att_s, const float* __restrict__ att_d) {
    __shared__ float Ws[HH * HID];  // 16 KB
    __shared__ float xs[8][HH];     // 4 KB
    int tid = threadIdx.x;
    for (int t = tid; t < HH * HID; t += 256) Ws[t] = W2[t];
    int w = tid >> 5, lane = tid & 31;
    int n = blockIdx.x * 8 + w;
    if (n < NN)
        *(float4*)&xs[w][lane * 4] = *(const float4*)&d_out1[(size_t)n * HH + lane * 4];
    __syncthreads();
    if (n >= NN) return;
    float acc = 0.0f;
#pragma unroll 8
    for (int k = 0; k < HH; k++) acc += xs[w][k] * Ws[k * HID + lane];
    d_h2[n * HID + lane] = acc;
    float s = acc * att_s[lane], t = acc * att_d[lane];
#pragma unroll
    for (int o = 16; o; o >>= 1) {
        s += __shfl_xor_sync(0xffffffffu, s, o);
        t += __shfl_xor_sync(0xffffffffu, t, o);
    }
    if (lane == 0) { d_as2[n] = s; d_ad2[n] = t; }
}

// ---------------- layer 2: edge passes (H=1) ----------------
__global__ void k_emax2(const int* __restrict__ ei) {
    int id = blockIdx.x * blockDim.x + threadIdx.x;
    if (id >= ET) return;
    int s, d; edge_sd(ei, id, s, d);
    float v = lrelu(d_as2[s] + d_ad2[d]);
    d_e2[id] = v;
    atomicMaxF(&d_m2[d], v);
}

__global__ void k_eexp2(const int* __restrict__ ei) {
    int id = blockIdx.x * blockDim.x + threadIdx.x;
    if (id >= ET) return;
    int s, d; edge_sd(ei, id, s, d);
    (void)s;
    float p = __expf(d_e2[id] - d_m2[d]);
    d_e2[id] = p;
    atomicAdd(&d_den2[d], p);
}

__global__ void k_eagg2(const int* __restrict__ ei) {
    int gid  = blockIdx.x * blockDim.x + threadIdx.x;
    int w    = gid >> 5;
    if (w >= ET) return;
    int lane = gid & 31;
    int s, d; edge_sd(ei, w, s, d);
    float alpha = d_e2[w] / d_den2[d];
    atomicAdd(&d_out2[d * HID + lane], alpha * d_h2[s * HID + lane]);
}

// ---------------- finalize: ELU + classifier ----------------
__global__ void k_final(const float* __restrict__ b2, const float* __restrict__ lw,
                        const float* __restrict__ lb, float* __restrict__ out) {
    int gid  = blockIdx.x * blockDim.x + threadIdx.x;
    int w    = gid >> 5;
    if (w >= NN) return;
    int lane = gid & 31;
    float v = eluf(d_out2[w * HID + lane] + b2[lane]);
    float o0 = v * lw[lane * 2 + 0];
    float o1 = v * lw[lane * 2 + 1];
#pragma unroll
    for (int o = 16; o; o >>= 1) {
        o0 += __shfl_xor_sync(0xffffffffu, o0, o);
        o1 += __shfl_xor_sync(0xffffffffu, o1, o);
    }
    if (lane == 0) { out[w * 2 + 0] = o0 + lb[0]; out[w * 2 + 1] = o1 + lb[1]; }
}

// ---------------- launch ----------------
extern "C" void kernel_launch(void* const* d_in, const int* in_sizes, int n_in,
                              void* d_out, int out_size) {
    const float* x        = (const float*)d_in[0];
    const int*   ei       = (const int*)  d_in[1];
    const float* W1       = (const float*)d_in[2];
    const float* att_src1 = (const float*)d_in[3];
    const float* att_dst1 = (const float*)d_in[4];
    const float* b1       = (const float*)d_in[5];
    const float* W2       = (const float*)d_in[6];
    const float* att_src2 = (const float*)d_in[7];
    const float* att_dst2 = (const float*)d_in[8];
    const float* b2       = (const float*)d_in[9];
    const float* lin_w    = (const float*)d_in[10];
    const float* lin_b    = (const float*)d_in[11];
    float* out = (float*)d_out;
    (void)in_sizes; (void)n_in; (void)out_size;

    const int EB = (ET + 255) / 256;          // edge-parallel blocks
    const int WB = (ET * 32 + 255) / 256;     // warp-per-edge blocks
    const int NB = (NN + 7) / 8;              // node blocks (8 rows each)

    k_init1<<<2048, 256>>>();
    k_init2<<<512, 256>>>();

    // layer 1
    k_gemm1<<<NB, 128>>>(x, W1, att_src1, att_dst1);
    k_emax1<<<EB, 256>>>(ei);
    k_eexp1<<<EB, 256>>>(ei);
    k_eagg1<<<WB, 256>>>(ei);
    k_fin1<<<2048, 256>>>(b1);

    // layer 2
    k_gemm2<<<NB, 256>>>(W2, att_src2, att_dst2);
    k_emax2<<<EB, 256>>>(ei);
    k_eexp2<<<EB, 256>>>(ei);
    k_eagg2<<<WB, 256>>>(ei);

    // classifier
    k_final<<<(NN * 32 + 255) / 256, 256>>>(b2, lin_w, lin_b, out);
}

// round 2
// speedup vs baseline: 1.0028x; 1.0028x over previous
#include <cuda_runtime.h>
#include <math.h>

// Problem constants (fixed shapes from reference)
#define NN    50000
#define EE    800000
#define ET    (EE + NN)          // edges + self loops
#define IND   256
#define HID   32
#define HEADS 4
#define HH    (HEADS * HID)      // 128
#define SLOPE 0.2f

// ---------------- scratch (device globals; no allocations) ----------------
__device__ float d_h1 [NN * HH];
__device__ float d_as1[NN * HEADS];
__device__ float d_ad1[NN * HEADS];
__device__ float d_m1 [NN * HEADS];
__device__ float d_den1[NN * HEADS];
__device__ float d_e1 [ET * HEADS];
__device__ float d_out1[NN * HH];

__device__ float d_h2 [NN * HID];
__device__ float d_as2[NN];
__device__ float d_ad2[NN];
__device__ float d_m2 [NN];
__device__ float d_den2[NN];
__device__ float d_e2 [ET];
__device__ float d_out2[NN * HID];

// ---------------- helpers ----------------
__device__ __forceinline__ void atomicMaxF(float* addr, float v) {
    if (v >= 0.0f) atomicMax((int*)addr, __float_as_int(v));
    else           atomicMin((unsigned int*)addr, __float_as_uint(v));
}

__device__ __forceinline__ void edge_sd(const int* __restrict__ ei, int id, int& s, int& d) {
    if (id < EE) { s = ei[id]; d = ei[EE + id]; }
    else         { s = id - EE; d = id - EE; }
}

__device__ __forceinline__ float lrelu(float v) { return v > 0.0f ? v : SLOPE * v; }
__device__ __forceinline__ float eluf (float v) { return v > 0.0f ? v : __expf(v) - 1.0f; }

// ---------------- init kernels ----------------
__global__ void k_init1() {
    int i = blockIdx.x * blockDim.x + threadIdx.x;
    int stride = gridDim.x * blockDim.x;
    for (int t = i; t < NN * HEADS; t += stride) { d_m1[t] = -3.4e38f; d_den1[t] = 0.0f; }
    for (int t = i; t < NN * HH; t += stride)    d_out1[t] = 0.0f;
}
__global__ void k_init2() {
    int i = blockIdx.x * blockDim.x + threadIdx.x;
    int stride = gridDim.x * blockDim.x;
    for (int t = i; t < NN; t += stride) { d_m2[t] = -3.4e38f; d_den2[t] = 0.0f; }
    for (int t = i; t < NN * HID; t += stride)   d_out2[t] = 0.0f;
}

// ---------------- layer 1: GEMM + attention scalars ----------------
// 8 node-rows per block, 128 threads (thread j = out column j)
__global__ void k_gemm1(const float* __restrict__ x, const float* __restrict__ W,
                        const float* __restrict__ att_s, const float* __restrict__ att_d) {
    __shared__ float xs[8 * IND];
    int n0 = blockIdx.x * 8;
    int j  = threadIdx.x;

    const float4* x4  = (const float4*)(x + (size_t)n0 * IND);
    float4*       xs4 = (float4*)xs;
#pragma unroll
    for (int t = 0; t < 4; t++) xs4[j + t * 128] = x4[j + t * 128];
    __syncthreads();

    float a[8];
#pragma unroll
    for (int r = 0; r < 8; r++) a[r] = 0.0f;

#pragma unroll 4
    for (int k = 0; k < IND; k++) {
        float w = W[k * HH + j];
#pragma unroll
        for (int r = 0; r < 8; r++) a[r] += xs[r * IND + k] * w;
    }

    int lane = j & 31, head = j >> 5;
    float es = att_s[head * HID + lane];
    float ed = att_d[head * HID + lane];

#pragma unroll
    for (int r = 0; r < 8; r++) {
        int n = n0 + r;
        if (n < NN) d_h1[(size_t)n * HH + j] = a[r];
        float s = a[r] * es, t = a[r] * ed;
#pragma unroll
        for (int o = 16; o; o >>= 1) {
            s += __shfl_xor_sync(0xffffffffu, s, o);
            t += __shfl_xor_sync(0xffffffffu, t, o);
        }
        if (lane == 0 && n < NN) { d_as1[n * HEADS + head] = s; d_ad1[n * HEADS + head] = t; }
    }
}

// ---------------- layer 1: edge passes ----------------
__global__ void k_emax1(const int* __restrict__ ei) {
    int id = blockIdx.x * blockDim.x + threadIdx.x;
    if (id >= ET) return;
    int s, d; edge_sd(ei, id, s, d);
    float4 sa = *(const float4*)&d_as1[s * 4];
    float4 da = *(const float4*)&d_ad1[d * 4];
    float v0 = lrelu(sa.x + da.x);
    float v1 = lrelu(sa.y + da.y);
    float v2 = lrelu(sa.z + da.z);
    float v3 = lrelu(sa.w + da.w);
    *(float4*)&d_e1[(size_t)id * 4] = make_float4(v0, v1, v2, v3);
    atomicMaxF(&d_m1[d * 4 + 0], v0);
    atomicMaxF(&d_m1[d * 4 + 1], v1);
    atomicMaxF(&d_m1[d * 4 + 2], v2);
    atomicMaxF(&d_m1[d * 4 + 3], v3);
}

__global__ void k_eexp1(const int* __restrict__ ei) {
    int id = blockIdx.x * blockDim.x + threadIdx.x;
    if (id >= ET) return;
    int s, d; edge_sd(ei, id, s, d);
    (void)s;
    float4 ev = *(const float4*)&d_e1[(size_t)id * 4];
    float4 mv = *(const float4*)&d_m1[d * 4];
    float p0 = __expf(ev.x - mv.x);
    float p1 = __expf(ev.y - mv.y);
    float p2 = __expf(ev.z - mv.z);
    float p3 = __expf(ev.w - mv.w);
    *(float4*)&d_e1[(size_t)id * 4] = make_float4(p0, p1, p2, p3);
    atomicAdd(&d_den1[d * 4 + 0], p0);
    atomicAdd(&d_den1[d * 4 + 1], p1);
    atomicAdd(&d_den1[d * 4 + 2], p2);
    atomicAdd(&d_den1[d * 4 + 3], p3);
}

// warp per edge; lane handles 4 contiguous columns (one head per 8 lanes)
__global__ void k_eagg1(const int* __restrict__ ei) {
    int gid  = blockIdx.x * blockDim.x + threadIdx.x;
    int w    = gid >> 5;
    if (w >= ET) return;
    int lane = gid & 31;
    int s, d; edge_sd(ei, w, s, d);
    int h = lane >> 3;
    float alpha = d_e1[(size_t)w * 4 + h] / d_den1[d * 4 + h];
    float4 hv = *(const float4*)&d_h1[(size_t)s * HH + lane * 4];
    float* o = &d_out1[(size_t)d * HH + lane * 4];
    atomicAdd(o + 0, alpha * hv.x);
    atomicAdd(o + 1, alpha * hv.y);
    atomicAdd(o + 2, alpha * hv.z);
    atomicAdd(o + 3, alpha * hv.w);
}

__global__ void k_fin1(const float* __restrict__ b1) {
    int i = blockIdx.x * blockDim.x + threadIdx.x;
    int stride = gridDim.x * blockDim.x;
    for (int t = i; t < NN * HH; t += stride) {
        float v = d_out1[t] + b1[t & (HH - 1)];
        d_out1[t] = eluf(v);
    }
}

// ---------------- layer 2: GEMM + attention scalars ----------------
// 8 nodes per block, 256 threads; warp w = node n0+w, lane = out column
__global__ void k_gemm2(const float* __restrict__ W2,
                        const float* __restrict__ att_s, const float* __restrict__ att_d) {
    __shared__ float Ws[HH * HID];  // 16 KB
    __shared__ float xs[8][HH];     // 4 KB
    int tid = threadIdx.x;
    for (int t = tid; t < HH * HID; t += 256) Ws[t] = W2[t];
    int w = tid >> 5, lane = tid & 31;
    int n = blockIdx.x * 8 + w;
    if (n < NN)
        *(float4*)&xs[w][lane * 4] = *(const float4*)&d_out1[(size_t)n * HH + lane * 4];
    __syncthreads();
    if (n >= NN) return;
    float acc = 0.0f;
#pragma unroll 8
    for (int k = 0; k < HH; k++) acc += xs[w][k] * Ws[k * HID + lane];
    d_h2[n * HID + lane] = acc;
    float s = acc * att_s[lane], t = acc * att_d[lane];
#pragma unroll
    for (int o = 16; o; o >>= 1) {
        s += __shfl_xor_sync(0xffffffffu, s, o);
        t += __shfl_xor_sync(0xffffffffu, t, o);
    }
    if (lane == 0) { d_as2[n] = s; d_ad2[n] = t; }
}

// ---------------- layer 2: edge passes (H=1) ----------------
__global__ void k_emax2(const int* __restrict__ ei) {
    int id = blockIdx.x * blockDim.x + threadIdx.x;
    if (id >= ET) return;
    int s, d; edge_sd(ei, id, s, d);
    float v = lrelu(d_as2[s] + d_ad2[d]);
    d_e2[id] = v;
    atomicMaxF(&d_m2[d], v);
}

__global__ void k_eexp2(const int* __restrict__ ei) {
    int id = blockIdx.x * blockDim.x + threadIdx.x;
    if (id >= ET) return;
    int s, d; edge_sd(ei, id, s, d);
    (void)s;
    float p = __expf(d_e2[id] - d_m2[d]);
    d_e2[id] = p;
    atomicAdd(&d_den2[d], p);
}

__global__ void k_eagg2(const int* __restrict__ ei) {
    int gid  = blockIdx.x * blockDim.x + threadIdx.x;
    int w    = gid >> 5;
    if (w >= ET) return;
    int lane = gid & 31;
    int s, d; edge_sd(ei, w, s, d);
    float alpha = d_e2[w] / d_den2[d];
    atomicAdd(&d_out2[d * HID + lane], alpha * d_h2[s * HID + lane]);
}

// ---------------- finalize: ELU + classifier ----------------
__global__ void k_final(const float* __restrict__ b2, const float* __restrict__ lw,
                        const float* __restrict__ lb, float* __restrict__ out) {
    int gid  = blockIdx.x * blockDim.x + threadIdx.x;
    int w    = gid >> 5;
    if (w >= NN) return;
    int lane = gid & 31;
    float v = eluf(d_out2[w * HID + lane] + b2[lane]);
    float o0 = v * lw[lane * 2 + 0];
    float o1 = v * lw[lane * 2 + 1];
#pragma unroll
    for (int o = 16; o; o >>= 1) {
        o0 += __shfl_xor_sync(0xffffffffu, o0, o);
        o1 += __shfl_xor_sync(0xffffffffu, o1, o);
    }
    if (lane == 0) { out[w * 2 + 0] = o0 + lb[0]; out[w * 2 + 1] = o1 + lb[1]; }
}

// ---------------- launch ----------------
extern "C" void kernel_launch(void* const* d_in, const int* in_sizes, int n_in,
                              void* d_out, int out_size) {
    const float* x        = (const float*)d_in[0];
    const int*   ei       = (const int*)  d_in[1];
    const float* W1       = (const float*)d_in[2];
    const float* att_src1 = (const float*)d_in[3];
    const float* att_dst1 = (const float*)d_in[4];
    const float* b1       = (const float*)d_in[5];
    const float* W2       = (const float*)d_in[6];
    const float* att_src2 = (const float*)d_in[7];
    const float* att_dst2 = (const float*)d_in[8];
    const float* b2       = (const float*)d_in[9];
    const float* lin_w    = (const float*)d_in[10];
    const float* lin_b    = (const float*)d_in[11];
    float* out = (float*)d_out;
    (void)in_sizes; (void)n_in; (void)out_size;

    const int EB = (ET + 255) / 256;          // edge-parallel blocks
    const int WB = (ET * 32 + 255) / 256;     // warp-per-edge blocks
    const int NB = (NN + 7) / 8;              // node blocks (8 rows each)

    k_init1<<<2048, 256>>>();
    k_init2<<<512, 256>>>();

    // layer 1
    k_gemm1<<<NB, 128>>>(x, W1, att_src1, att_dst1);
    k_emax1<<<EB, 256>>>(ei);
    k_eexp1<<<EB, 256>>>(ei);
    k_eagg1<<<WB, 256>>>(ei);
    k_fin1<<<2048, 256>>>(b1);

    // layer 2
    k_gemm2<<<NB, 256>>>(W2, att_src2, att_dst2);
    k_emax2<<<EB, 256>>>(ei);
    k_eexp2<<<EB, 256>>>(ei);
    k_eagg2<<<WB, 256>>>(ei);

    // classifier
    k_final<<<(NN * 32 + 255) / 256, 256>>>(b2, lin_w, lin_b, out);
}

// round 3
// speedup vs baseline: 1.6043x; 1.5998x over previous
#include <cuda_runtime.h>
#include <math.h>

// Problem constants (fixed shapes from reference)
#define NN    50000
#define EE    800000
#define ET    (EE + NN)          // edges + self loops
#define IND   256
#define HID   32
#define HEADS 4
#define HH    (HEADS * HID)      // 128
#define SLOPE 0.2f

// ---------------- scratch (device globals; no allocations) ----------------
__device__ float d_h1 [NN * HH];
__device__ float d_as1[NN * HEADS];
__device__ float d_ad1[NN * HEADS];
__device__ float d_den1[NN * HEADS];
__device__ float d_out1[NN * HH];

__device__ float d_h2 [NN * HID];
__device__ float d_as2[NN];
__device__ float d_ad2[NN];
__device__ float d_den2[NN];
__device__ float d_out2[NN * HID];

// ---------------- helpers ----------------
__device__ __forceinline__ void edge_sd(const int* __restrict__ ei, int id, int& s, int& d) {
    if (id < EE) { s = __ldg(&ei[id]); d = __ldg(&ei[EE + id]); }
    else         { s = id - EE; d = id - EE; }
}

__device__ __forceinline__ float lrelu(float v) { return v > 0.0f ? v : SLOPE * v; }
__device__ __forceinline__ float eluf (float v) { return v > 0.0f ? v : __expf(v) - 1.0f; }

// packed f32x2 helpers (Blackwell packed-fp32 pipe)
__device__ __forceinline__ unsigned long long packf2(float lo, float hi) {
    unsigned long long r;
    asm("mov.b64 %0, {%1, %2};" : "=l"(r) : "f"(lo), "f"(hi));
    return r;
}
__device__ __forceinline__ void fma2(unsigned long long& d, unsigned long long a, unsigned long long b) {
    asm("fma.rn.f32x2 %0, %1, %2, %0;" : "+l"(d) : "l"(a), "l"(b));
}
__device__ __forceinline__ float unpack_sum(unsigned long long v) {
    float lo = __uint_as_float((unsigned int)(v & 0xffffffffull));
    float hi = __uint_as_float((unsigned int)(v >> 32));
    return lo + hi;
}

// ---------------- init ----------------
__global__ void k_init() {
    int i = blockIdx.x * blockDim.x + threadIdx.x;
    int stride = gridDim.x * blockDim.x;
    for (int t = i; t < NN * HEADS; t += stride) d_den1[t] = 0.0f;
    for (int t = i; t < NN; t += stride)         d_den2[t] = 0.0f;
    float4 z = make_float4(0.f, 0.f, 0.f, 0.f);
    for (int t = i; t < NN * HH / 4; t += stride)  ((float4*)d_out1)[t] = z;
    for (int t = i; t < NN * HID / 4; t += stride) ((float4*)d_out2)[t] = z;
}

// ---------------- layer 1: GEMM (f32x2 packed) + attention scalars ----------------
// 8 node-rows per block, 128 threads (thread j = out column j)
__global__ void k_gemm1(const float* __restrict__ x, const float* __restrict__ W,
                        const float* __restrict__ att_s, const float* __restrict__ att_d) {
    __shared__ float xs[8 * IND];
    int n0 = blockIdx.x * 8;
    int j  = threadIdx.x;

    const float4* x4  = (const float4*)(x + (size_t)n0 * IND);
    float4*       xs4 = (float4*)xs;
#pragma unroll
    for (int t = 0; t < 4; t++) xs4[j + t * 128] = x4[j + t * 128];
    __syncthreads();

    unsigned long long acc[8];
#pragma unroll
    for (int r = 0; r < 8; r++) acc[r] = 0ull;

#pragma unroll 4
    for (int k = 0; k < IND; k += 4) {
        float w0 = __ldg(&W[(k + 0) * HH + j]);
        float w1 = __ldg(&W[(k + 1) * HH + j]);
        float w2 = __ldg(&W[(k + 2) * HH + j]);
        float w3 = __ldg(&W[(k + 3) * HH + j]);
        unsigned long long w01 = packf2(w0, w1);
        unsigned long long w23 = packf2(w2, w3);
#pragma unroll
        for (int r = 0; r < 8; r++) {
            ulonglong2 xv = *(const ulonglong2*)&xs[r * IND + k];
            fma2(acc[r], xv.x, w01);
            fma2(acc[r], xv.y, w23);
        }
    }

    int lane = j & 31, head = j >> 5;
    float es = att_s[head * HID + lane];
    float ed = att_d[head * HID + lane];

#pragma unroll
    for (int r = 0; r < 8; r++) {
        int n = n0 + r;
        float a = unpack_sum(acc[r]);
        d_h1[(size_t)n * HH + j] = a;
        float s = a * es, t = a * ed;
#pragma unroll
        for (int o = 16; o; o >>= 1) {
            s += __shfl_xor_sync(0xffffffffu, s, o);
            t += __shfl_xor_sync(0xffffffffu, t, o);
        }
        if (lane == 0) { d_as1[n * HEADS + head] = s; d_ad1[n * HEADS + head] = t; }
    }
}

// ---------------- layer 1: fused edge pass (exp + denom + aggregate) ----------------
// warp per edge; lane handles 4 contiguous columns (head = lane>>3)
__global__ void k_edge1(const int* __restrict__ ei) {
    int gid  = blockIdx.x * blockDim.x + threadIdx.x;
    int w    = gid >> 5;
    if (w >= ET) return;
    int lane = gid & 31;
    int s, d; edge_sd(ei, w, s, d);
    int h = lane >> 3;
    float e = lrelu(d_as1[s * 4 + h] + d_ad1[d * 4 + h]);
    float p = __expf(e);
    if ((lane & 7) == 0) atomicAdd(&d_den1[d * 4 + h], p);
    float4 hv = *(const float4*)&d_h1[(size_t)s * HH + lane * 4];
    float4 v  = make_float4(p * hv.x, p * hv.y, p * hv.z, p * hv.w);
    atomicAdd((float4*)&d_out1[(size_t)d * HH + lane * 4], v);
}

// normalize + bias + ELU   (one float4 per thread)
__global__ void k_norm1(const float* __restrict__ b1) {
    int i = blockIdx.x * blockDim.x + threadIdx.x;
    if (i >= NN * (HH / 4)) return;
    int n = i >> 5, q = i & 31;
    float inv = 1.0f / d_den1[n * 4 + (q >> 3)];
    float4 v  = *(float4*)&d_out1[(size_t)n * HH + q * 4];
    float4 bb = *(const float4*)&b1[q * 4];
    v.x = eluf(v.x * inv + bb.x);
    v.y = eluf(v.y * inv + bb.y);
    v.z = eluf(v.z * inv + bb.z);
    v.w = eluf(v.w * inv + bb.w);
    *(float4*)&d_out1[(size_t)n * HH + q * 4] = v;
}

// ---------------- layer 2: GEMM + attention scalars ----------------
// 8 nodes per block, 256 threads; warp w = node n0+w, lane = out column
__global__ void k_gemm2(const float* __restrict__ W2,
                        const float* __restrict__ att_s, const float* __restrict__ att_d) {
    __shared__ float Ws[HH * HID];  // 16 KB
    __shared__ float xs[8][HH];     // 4 KB
    int tid = threadIdx.x;
    for (int t = tid; t < HH * HID; t += 256) Ws[t] = W2[t];
    int w = tid >> 5, lane = tid & 31;
    int n = blockIdx.x * 8 + w;
    if (n < NN)
        *(float4*)&xs[w][lane * 4] = *(const float4*)&d_out1[(size_t)n * HH + lane * 4];
    __syncthreads();
    if (n >= NN) return;
    float acc = 0.0f;
#pragma unroll 8
    for (int k = 0; k < HH; k += 4) {
        float4 xv = *(const float4*)&xs[w][k];
        acc += xv.x * Ws[(k + 0) * HID + lane];
        acc += xv.y * Ws[(k + 1) * HID + lane];
        acc += xv.z * Ws[(k + 2) * HID + lane];
        acc += xv.w * Ws[(k + 3) * HID + lane];
    }
    d_h2[n * HID + lane] = acc;
    float s = acc * att_s[lane], t = acc * att_d[lane];
#pragma unroll
    for (int o = 16; o; o >>= 1) {
        s += __shfl_xor_sync(0xffffffffu, s, o);
        t += __shfl_xor_sync(0xffffffffu, t, o);
    }
    if (lane == 0) { d_as2[n] = s; d_ad2[n] = t; }
}

// ---------------- layer 2: fused edge pass (8 lanes per edge) ----------------
__global__ void k_edge2(const int* __restrict__ ei) {
    int gid = blockIdx.x * blockDim.x + threadIdx.x;
    int e   = gid >> 3;
    if (e >= ET) return;
    int g = gid & 7;
    int s, d; edge_sd(ei, e, s, d);
    float p = __expf(lrelu(d_as2[s] + d_ad2[d]));
    if (g == 0) atomicAdd(&d_den2[d], p);
    float4 hv = *(const float4*)&d_h2[s * HID + g * 4];
    float4 v  = make_float4(p * hv.x, p * hv.y, p * hv.z, p * hv.w);
    atomicAdd((float4*)&d_out2[d * HID + g * 4], v);
}

// ---------------- finalize: normalize + bias + ELU + classifier ----------------
__global__ void k_final(const float* __restrict__ b2, const float* __restrict__ lw,
                        const float* __restrict__ lb, float* __restrict__ out) {
    int gid  = blockIdx.x * blockDim.x + threadIdx.x;
    int w    = gid >> 5;
    if (w >= NN) return;
    int lane = gid & 31;
    float inv = 1.0f / d_den2[w];
    float v = eluf(d_out2[w * HID + lane] * inv + b2[lane]);
    float o0 = v * lw[lane * 2 + 0];
    float o1 = v * lw[lane * 2 + 1];
#pragma unroll
    for (int o = 16; o; o >>= 1) {
        o0 += __shfl_xor_sync(0xffffffffu, o0, o);
        o1 += __shfl_xor_sync(0xffffffffu, o1, o);
    }
    if (lane == 0) { out[w * 2 + 0] = o0 + lb[0]; out[w * 2 + 1] = o1 + lb[1]; }
}

// ---------------- launch ----------------
extern "C" void kernel_launch(void* const* d_in, const int* in_sizes, int n_in,
                              void* d_out, int out_size) {
    const float* x        = (const float*)d_in[0];
    const int*   ei       = (const int*)  d_in[1];
    const float* W1       = (const float*)d_in[2];
    const float* att_src1 = (const float*)d_in[3];
    const float* att_dst1 = (const float*)d_in[4];
    const float* b1       = (const float*)d_in[5];
    const float* W2       = (const float*)d_in[6];
    const float* att_src2 = (const float*)d_in[7];
    const float* att_dst2 = (const float*)d_in[8];
    const float* b2       = (const float*)d_in[9];
    const float* lin_w    = (const float*)d_in[10];
    const float* lin_b    = (const float*)d_in[11];
    float* out = (float*)d_out;
    (void)in_sizes; (void)n_in; (void)out_size;

    const int NB  = NN / 8;                       // 6250 node blocks (8 rows each)
    const int WB1 = (ET * 32 + 255) / 256;        // warp-per-edge blocks (layer 1)
    const int WB2 = (ET * 8  + 255) / 256;        // 8-lanes-per-edge blocks (layer 2)

    k_init<<<2048, 256>>>();

    // layer 1
    k_gemm1<<<NB, 128>>>(x, W1, att_src1, att_dst1);
    k_edge1<<<WB1, 256>>>(ei);
    k_norm1<<<(NN * 32 + 255) / 256, 256>>>(b1);

    // layer 2
    k_gemm2<<<NB, 256>>>(W2, att_src2, att_dst2);
    k_edge2<<<WB2, 256>>>(ei);

    // classifier
    k_final<<<(NN * 32 + 255) / 256, 256>>>(b2, lin_w, lin_b, out);
}

// round 4
// speedup vs baseline: 1.8642x; 1.1620x over previous
#include <cuda_runtime.h>
#include <math.h>

// Problem constants (fixed shapes from reference)
#define NN    50000
#define EE    800000
#define ET    (EE + NN)          // edges + self loops
#define IND   256
#define HID   32
#define HEADS 4
#define HH    (HEADS * HID)      // 128
#define SLOPE 0.2f

// ---------------- scratch (device globals; no allocations) ----------------
__device__ float d_h1 [NN * HH];
__device__ float d_as1[NN * HEADS];
__device__ float d_ad1[NN * HEADS];
__device__ float d_out1[NN * HH];

__device__ float d_h2 [NN * HID];
__device__ float d_as2[NN];
__device__ float d_ad2[NN];

// CSR scratch
__device__ int d_cnt   [NN];
__device__ int d_cnt2  [NN];
__device__ int d_rowptr[NN + 1];
__device__ int d_esrc  [ET];

// ---------------- helpers ----------------
__device__ __forceinline__ float lrelu(float v) { return v > 0.0f ? v : SLOPE * v; }
__device__ __forceinline__ float eluf (float v) { return v > 0.0f ? v : __expf(v) - 1.0f; }

// packed f32x2 helpers (Blackwell packed-fp32 pipe)
__device__ __forceinline__ unsigned long long packf2(float lo, float hi) {
    unsigned long long r;
    asm("mov.b64 %0, {%1, %2};" : "=l"(r) : "f"(lo), "f"(hi));
    return r;
}
__device__ __forceinline__ void fma2(unsigned long long& d, unsigned long long a, unsigned long long b) {
    asm("fma.rn.f32x2 %0, %1, %2, %0;" : "+l"(d) : "l"(a), "l"(b));
}
__device__ __forceinline__ float unpack_sum(unsigned long long v) {
    float lo = __uint_as_float((unsigned int)(v & 0xffffffffull));
    float hi = __uint_as_float((unsigned int)(v >> 32));
    return lo + hi;
}

// ---------------- CSR build ----------------
__global__ void k_zero() {
    int i = blockIdx.x * blockDim.x + threadIdx.x;
    int stride = gridDim.x * blockDim.x;
    for (int t = i; t < NN; t += stride) { d_cnt[t] = 1; d_cnt2[t] = 0; }  // cnt=1: self loop
}

__global__ void k_hist(const int* __restrict__ ei) {
    int e = blockIdx.x * blockDim.x + threadIdx.x;
    if (e < EE) atomicAdd(&d_cnt[ei[EE + e]], 1);
}

// single block, 1024 threads: exclusive scan of d_cnt -> d_rowptr
__global__ void k_scan() {
    __shared__ int sh[1024];
    const int CH = (NN + 1023) / 1024;  // 49
    int t = threadIdx.x;
    int base = t * CH;
    int local = 0;
    for (int i = 0; i < CH; i++) {
        int idx = base + i;
        if (idx < NN) local += d_cnt[idx];
    }
    sh[t] = local;
    __syncthreads();
    for (int off = 1; off < 1024; off <<= 1) {
        int v = 0;
        if (t >= off) v = sh[t - off];
        __syncthreads();
        if (t >= off) sh[t] += v;
        __syncthreads();
    }
    int run = sh[t] - local;   // exclusive prefix
    for (int i = 0; i < CH; i++) {
        int idx = base + i;
        if (idx < NN) { d_rowptr[idx] = run; run += d_cnt[idx]; }
    }
    if (t == 1023) d_rowptr[NN] = ET;
}

__global__ void k_scatter(const int* __restrict__ ei) {
    int id = blockIdx.x * blockDim.x + threadIdx.x;
    if (id >= ET) return;
    int s, d;
    if (id < EE) { s = ei[id]; d = ei[EE + id]; }
    else         { s = id - EE; d = id - EE; }
    int pos = d_rowptr[d] + atomicAdd(&d_cnt2[d], 1);
    d_esrc[pos] = s;
}

// ---------------- layer 1: GEMM (f32x2 packed) + attention scalars ----------------
// 8 node-rows per block, 128 threads (thread j = out column j)
__global__ void k_gemm1(const float* __restrict__ x, const float* __restrict__ W,
                        const float* __restrict__ att_s, const float* __restrict__ att_d) {
    __shared__ float xs[8 * IND];
    int n0 = blockIdx.x * 8;
    int j  = threadIdx.x;

    const float4* x4  = (const float4*)(x + (size_t)n0 * IND);
    float4*       xs4 = (float4*)xs;
#pragma unroll
    for (int t = 0; t < 4; t++) xs4[j + t * 128] = x4[j + t * 128];
    __syncthreads();

    unsigned long long acc[8];
#pragma unroll
    for (int r = 0; r < 8; r++) acc[r] = 0ull;

#pragma unroll 4
    for (int k = 0; k < IND; k += 4) {
        float w0 = __ldg(&W[(k + 0) * HH + j]);
        float w1 = __ldg(&W[(k + 1) * HH + j]);
        float w2 = __ldg(&W[(k + 2) * HH + j]);
        float w3 = __ldg(&W[(k + 3) * HH + j]);
        unsigned long long w01 = packf2(w0, w1);
        unsigned long long w23 = packf2(w2, w3);
#pragma unroll
        for (int r = 0; r < 8; r++) {
            ulonglong2 xv = *(const ulonglong2*)&xs[r * IND + k];
            fma2(acc[r], xv.x, w01);
            fma2(acc[r], xv.y, w23);
        }
    }

    int lane = j & 31, head = j >> 5;
    float es = att_s[head * HID + lane];
    float ed = att_d[head * HID + lane];

#pragma unroll
    for (int r = 0; r < 8; r++) {
        int n = n0 + r;
        float a = unpack_sum(acc[r]);
        d_h1[(size_t)n * HH + j] = a;
        float s = a * es, t = a * ed;
#pragma unroll
        for (int o = 16; o; o >>= 1) {
            s += __shfl_xor_sync(0xffffffffu, s, o);
            t += __shfl_xor_sync(0xffffffffu, t, o);
        }
        if (lane == 0) { d_as1[n * HEADS + head] = s; d_ad1[n * HEADS + head] = t; }
    }
}

// ---------------- layer 1: CSR gather (softmax + aggregate + bias + ELU fused) ----------------
// one warp per destination node; lane covers cols [lane*4, lane*4+4), head = lane>>3
__global__ void k_gather1(const float* __restrict__ b1) {
    int gid  = blockIdx.x * blockDim.x + threadIdx.x;
    int n    = gid >> 5;
    if (n >= NN) return;
    int lane = gid & 31;
    int h    = lane >> 3;

    int start = d_rowptr[n], end = d_rowptr[n + 1];
    float ad = d_ad1[n * 4 + h];

    float4 acc = make_float4(0.f, 0.f, 0.f, 0.f);
    float  den = 0.f;

    for (int j = start; j < end; j++) {
        int s = __ldg(&d_esrc[j]);
        float p = __expf(lrelu(__ldg(&d_as1[s * 4 + h]) + ad));
        float4 hv = *(const float4*)&d_h1[(size_t)s * HH + lane * 4];
        den  += p;
        acc.x = fmaf(p, hv.x, acc.x);
        acc.y = fmaf(p, hv.y, acc.y);
        acc.z = fmaf(p, hv.z, acc.z);
        acc.w = fmaf(p, hv.w, acc.w);
    }

    float inv = 1.0f / den;
    float4 bb = *(const float4*)&b1[lane * 4];
    acc.x = eluf(acc.x * inv + bb.x);
    acc.y = eluf(acc.y * inv + bb.y);
    acc.z = eluf(acc.z * inv + bb.z);
    acc.w = eluf(acc.w * inv + bb.w);
    *(float4*)&d_out1[(size_t)n * HH + lane * 4] = acc;
}

// ---------------- layer 2: GEMM + attention scalars ----------------
__global__ void k_gemm2(const float* __restrict__ W2,
                        const float* __restrict__ att_s, const float* __restrict__ att_d) {
    __shared__ float Ws[HH * HID];  // 16 KB
    __shared__ float xs[8][HH];     // 4 KB
    int tid = threadIdx.x;
    for (int t = tid; t < HH * HID; t += 256) Ws[t] = W2[t];
    int w = tid >> 5, lane = tid & 31;
    int n = blockIdx.x * 8 + w;
    if (n < NN)
        *(float4*)&xs[w][lane * 4] = *(const float4*)&d_out1[(size_t)n * HH + lane * 4];
    __syncthreads();
    if (n >= NN) return;
    float acc = 0.0f;
#pragma unroll 8
    for (int k = 0; k < HH; k += 4) {
        float4 xv = *(const float4*)&xs[w][k];
        acc += xv.x * Ws[(k + 0) * HID + lane];
        acc += xv.y * Ws[(k + 1) * HID + lane];
        acc += xv.z * Ws[(k + 2) * HID + lane];
        acc += xv.w * Ws[(k + 3) * HID + lane];
    }
    d_h2[n * HID + lane] = acc;
    float s = acc * att_s[lane], t = acc * att_d[lane];
#pragma unroll
    for (int o = 16; o; o >>= 1) {
        s += __shfl_xor_sync(0xffffffffu, s, o);
        t += __shfl_xor_sync(0xffffffffu, t, o);
    }
    if (lane == 0) { d_as2[n] = s; d_ad2[n] = t; }
}

// ---------------- layer 2: CSR gather + bias/ELU + classifier fused ----------------
// one warp per destination node; lane = column
__global__ void k_gather2(const float* __restrict__ b2, const float* __restrict__ lw,
                          const float* __restrict__ lb, float* __restrict__ out) {
    int gid  = blockIdx.x * blockDim.x + threadIdx.x;
    int n    = gid >> 5;
    if (n >= NN) return;
    int lane = gid & 31;

    int start = d_rowptr[n], end = d_rowptr[n + 1];
    float ad = d_ad2[n];

    float acc = 0.f, den = 0.f;
    for (int j = start; j < end; j++) {
        int s = __ldg(&d_esrc[j]);
        float p = __expf(lrelu(__ldg(&d_as2[s]) + ad));
        den += p;
        acc = fmaf(p, d_h2[s * HID + lane], acc);
    }

    float v = eluf(acc / den + b2[lane]);
    float o0 = v * lw[lane * 2 + 0];
    float o1 = v * lw[lane * 2 + 1];
#pragma unroll
    for (int o = 16; o; o >>= 1) {
        o0 += __shfl_xor_sync(0xffffffffu, o0, o);
        o1 += __shfl_xor_sync(0xffffffffu, o1, o);
    }
    if (lane == 0) { out[n * 2 + 0] = o0 + lb[0]; out[n * 2 + 1] = o1 + lb[1]; }
}

// ---------------- launch ----------------
extern "C" void kernel_launch(void* const* d_in, const int* in_sizes, int n_in,
                              void* d_out, int out_size) {
    const float* x        = (const float*)d_in[0];
    const int*   ei       = (const int*)  d_in[1];
    const float* W1       = (const float*)d_in[2];
    const float* att_src1 = (const float*)d_in[3];
    const float* att_dst1 = (const float*)d_in[4];
    const float* b1       = (const float*)d_in[5];
    const float* W2       = (const float*)d_in[6];
    const float* att_src2 = (const float*)d_in[7];
    const float* att_dst2 = (const float*)d_in[8];
    const float* b2       = (const float*)d_in[9];
    const float* lin_w    = (const float*)d_in[10];
    const float* lin_b    = (const float*)d_in[11];
    float* out = (float*)d_out;
    (void)in_sizes; (void)n_in; (void)out_size;

    const int NB = NN / 8;                        // 6250 node blocks
    const int GW = (NN * 32 + 255) / 256;         // warp-per-node blocks

    // CSR build (overlappable with gemm1 in issue order)
    k_zero<<<256, 256>>>();
    k_hist<<<(EE + 255) / 256, 256>>>(ei);
    k_scan<<<1, 1024>>>();
    k_scatter<<<(ET + 255) / 256, 256>>>(ei);

    // layer 1
    k_gemm1<<<NB, 128>>>(x, W1, att_src1, att_dst1);
    k_gather1<<<GW, 256>>>(b1);

    // layer 2
    k_gemm2<<<NB, 256>>>(W2, att_src2, att_dst2);
    k_gather2<<<GW, 256>>>(b2, lin_w, lin_b, out);
}

// round 5
// speedup vs baseline: 2.1301x; 1.1426x over previous
#include <cuda_runtime.h>
#include <math.h>

#define NN    50000
#define EE    800000
#define ET    (EE + NN)
#define IND   256
#define HID   32
#define HEADS 4
#define HH    (HEADS * HID)      // 128
#define SLOPE 0.2f
#define R1    32                 // rows per block in gemm1

// ---------------- scratch ----------------
__device__ float d_h1 [NN * HH];
__device__ float d_as1[NN * HEADS];
__device__ float d_ad1[NN * HEADS];
__device__ float d_out1[NN * HH];

__device__ float d_h2 [NN * HID];
__device__ float d_as2[NN];
__device__ float d_ad2[NN];

// CSR scratch
__device__ int d_cnt   [NN];
__device__ int d_cnt2  [NN];
__device__ int d_rowptr[NN + 1];
__device__ int d_esrc  [ET];
__device__ int d_bsum  [256];
__device__ int d_boff  [256];

#define SCAN_B 196               // ceil(50000/256)

// ---------------- helpers ----------------
__device__ __forceinline__ float lrelu(float v) { return v > 0.0f ? v : SLOPE * v; }
__device__ __forceinline__ float eluf (float v) { return v > 0.0f ? v : __expf(v) - 1.0f; }

__device__ __forceinline__ unsigned long long packf2(float lo, float hi) {
    unsigned long long r;
    asm("mov.b64 %0, {%1, %2};" : "=l"(r) : "f"(lo), "f"(hi));
    return r;
}
__device__ __forceinline__ void fma2(unsigned long long& d, unsigned long long a, unsigned long long b) {
    asm("fma.rn.f32x2 %0, %1, %2, %0;" : "+l"(d) : "l"(a), "l"(b));
}
__device__ __forceinline__ float unpack_sum(unsigned long long v) {
    float lo = __uint_as_float((unsigned int)(v & 0xffffffffull));
    float hi = __uint_as_float((unsigned int)(v >> 32));
    return lo + hi;
}

// ---------------- CSR build ----------------
__global__ void k_zero() {
    int i = blockIdx.x * blockDim.x + threadIdx.x;
    int stride = gridDim.x * blockDim.x;
    for (int t = i; t < NN; t += stride) { d_cnt[t] = 1; d_cnt2[t] = 0; }
}

__global__ void k_hist(const int* __restrict__ ei) {
    int e = blockIdx.x * blockDim.x + threadIdx.x;
    if (e < EE) atomicAdd(&d_cnt[ei[EE + e]], 1);
}

// phase A: per-block inclusive scan of 256 counts; local exclusive -> rowptr, total -> bsum
__global__ void k_scanA() {
    __shared__ int sh[256];
    int t = threadIdx.x;
    int idx = blockIdx.x * 256 + t;
    int c = (idx < NN) ? d_cnt[idx] : 0;
    sh[t] = c;
    __syncthreads();
#pragma unroll
    for (int off = 1; off < 256; off <<= 1) {
        int v = (t >= off) ? sh[t - off] : 0;
        __syncthreads();
        sh[t] += v;
        __syncthreads();
    }
    if (idx < NN) d_rowptr[idx] = sh[t] - c;     // local exclusive
    if (t == 255) d_bsum[blockIdx.x] = sh[255];
}

// phase B: scan block sums (1 block)
__global__ void k_scanB() {
    __shared__ int sh[256];
    int t = threadIdx.x;
    int c = (t < SCAN_B) ? d_bsum[t] : 0;
    sh[t] = c;
    __syncthreads();
#pragma unroll
    for (int off = 1; off < 256; off <<= 1) {
        int v = (t >= off) ? sh[t - off] : 0;
        __syncthreads();
        sh[t] += v;
        __syncthreads();
    }
    if (t < SCAN_B) d_boff[t] = sh[t] - c;       // exclusive
}

// phase C: add block offsets
__global__ void k_scanC() {
    int idx = blockIdx.x * 256 + threadIdx.x;
    if (idx < NN) d_rowptr[idx] += d_boff[blockIdx.x];
    if (idx == 0) d_rowptr[NN] = ET;
}

__global__ void k_scatter(const int* __restrict__ ei) {
    int id = blockIdx.x * blockDim.x + threadIdx.x;
    if (id >= ET) return;
    int s, d;
    if (id < EE) { s = ei[id]; d = ei[EE + id]; }
    else         { s = id - EE; d = id - EE; }
    int pos = d_rowptr[d] + atomicAdd(&d_cnt2[d], 1);
    d_esrc[pos] = s;
}

// ---------------- layer 1: GEMM (32 rows/block, f32x2) + attention scalars ----------------
__global__ void __launch_bounds__(128) k_gemm1(
        const float* __restrict__ x, const float* __restrict__ W,
        const float* __restrict__ att_s, const float* __restrict__ att_d) {
    __shared__ float xs[R1 * IND];   // 32 KB
    int n0 = blockIdx.x * R1;
    int j  = threadIdx.x;

    const float4* x4  = (const float4*)(x + (size_t)n0 * IND);
    float4*       xs4 = (float4*)xs;
    int lim = (NN - n0) * (IND / 4);            // float4 entries in range
#pragma unroll
    for (int t = 0; t < R1 * IND / 4 / 128; t++) {
        int idx = j + t * 128;
        xs4[idx] = (idx < lim) ? x4[idx] : make_float4(0.f, 0.f, 0.f, 0.f);
    }
    __syncthreads();

    unsigned long long acc[R1];
#pragma unroll
    for (int r = 0; r < R1; r++) acc[r] = 0ull;

    for (int k = 0; k < IND; k += 4) {
        float w0 = __ldg(&W[(k + 0) * HH + j]);
        float w1 = __ldg(&W[(k + 1) * HH + j]);
        float w2 = __ldg(&W[(k + 2) * HH + j]);
        float w3 = __ldg(&W[(k + 3) * HH + j]);
        unsigned long long w01 = packf2(w0, w1);
        unsigned long long w23 = packf2(w2, w3);
#pragma unroll
        for (int r = 0; r < R1; r++) {
            ulonglong2 xv = *(const ulonglong2*)&xs[r * IND + k];
            fma2(acc[r], xv.x, w01);
            fma2(acc[r], xv.y, w23);
        }
    }

    int lane = j & 31, head = j >> 5;
    float es = att_s[head * HID + lane];
    float ed = att_d[head * HID + lane];

#pragma unroll
    for (int r = 0; r < R1; r++) {
        int n = n0 + r;
        if (n >= NN) break;
        float a = unpack_sum(acc[r]);
        d_h1[(size_t)n * HH + j] = a;
        float s = a * es, t = a * ed;
#pragma unroll
        for (int o = 16; o; o >>= 1) {
            s += __shfl_xor_sync(0xffffffffu, s, o);
            t += __shfl_xor_sync(0xffffffffu, t, o);
        }
        if (lane == 0) { d_as1[n * HEADS + head] = s; d_ad1[n * HEADS + head] = t; }
    }
}

// ---------------- layer 1: CSR gather (chunked shuffle src distribution) ----------------
// one warp per destination node; lane covers cols [lane*4, lane*4+4), head = lane>>3
__global__ void k_gather1(const float* __restrict__ b1) {
    int gid  = blockIdx.x * blockDim.x + threadIdx.x;
    int n    = gid >> 5;
    if (n >= NN) return;
    int lane = gid & 31;
    int h    = lane >> 3;

    int start = d_rowptr[n], end = d_rowptr[n + 1];
    float ad = d_ad1[n * 4 + h];

    float4 acc = make_float4(0.f, 0.f, 0.f, 0.f);
    float  den = 0.f;

    for (int base = start; base < end; base += 32) {
        int m   = min(32, end - base);
        int myS = (lane < m) ? __ldg(&d_esrc[base + lane]) : 0;
#pragma unroll 4
        for (int i = 0; i < m; i++) {
            int s = __shfl_sync(0xffffffffu, myS, i);
            float p = __expf(lrelu(__ldg(&d_as1[s * 4 + h]) + ad));
            float4 hv = *(const float4*)&d_h1[(size_t)s * HH + lane * 4];
            den  += p;
            acc.x = fmaf(p, hv.x, acc.x);
            acc.y = fmaf(p, hv.y, acc.y);
            acc.z = fmaf(p, hv.z, acc.z);
            acc.w = fmaf(p, hv.w, acc.w);
        }
    }

    float inv = 1.0f / den;
    float4 bb = *(const float4*)&b1[lane * 4];
    acc.x = eluf(acc.x * inv + bb.x);
    acc.y = eluf(acc.y * inv + bb.y);
    acc.z = eluf(acc.z * inv + bb.z);
    acc.w = eluf(acc.w * inv + bb.w);
    *(float4*)&d_out1[(size_t)n * HH + lane * 4] = acc;
}

// ---------------- layer 2: GEMM (32 nodes/block) + attention scalars ----------------
__global__ void k_gemm2(const float* __restrict__ W2,
                        const float* __restrict__ att_s, const float* __restrict__ att_d) {
    __shared__ float Ws[HH * HID];    // 16 KB
    __shared__ float xs[32][HH];      // 16 KB
    int tid = threadIdx.x;
    for (int t = tid; t < HH * HID; t += 256) Ws[t] = W2[t];
    int w = tid >> 5, lane = tid & 31;
    int n0 = blockIdx.x * 32;
    // load 32 node rows: each warp loads 4 rows
#pragma unroll
    for (int r = 0; r < 4; r++) {
        int row = w * 4 + r;
        int n = n0 + row;
        if (n < NN)
            *(float4*)&xs[row][lane * 4] = *(const float4*)&d_out1[(size_t)n * HH + lane * 4];
    }
    __syncthreads();

    float as_l = att_s[lane], ad_l = att_d[lane];
#pragma unroll
    for (int r = 0; r < 4; r++) {
        int row = w * 4 + r;
        int n = n0 + row;
        if (n >= NN) break;
        float acc = 0.0f;
#pragma unroll 8
        for (int k = 0; k < HH; k += 4) {
            float4 xv = *(const float4*)&xs[row][k];
            acc += xv.x * Ws[(k + 0) * HID + lane];
            acc += xv.y * Ws[(k + 1) * HID + lane];
            acc += xv.z * Ws[(k + 2) * HID + lane];
            acc += xv.w * Ws[(k + 3) * HID + lane];
        }
        d_h2[n * HID + lane] = acc;
        float s = acc * as_l, t = acc * ad_l;
#pragma unroll
        for (int o = 16; o; o >>= 1) {
            s += __shfl_xor_sync(0xffffffffu, s, o);
            t += __shfl_xor_sync(0xffffffffu, t, o);
        }
        if (lane == 0) { d_as2[n] = s; d_ad2[n] = t; }
    }
}

// ---------------- layer 2: CSR gather + bias/ELU + classifier ----------------
__global__ void k_gather2(const float* __restrict__ b2, const float* __restrict__ lw,
                          const float* __restrict__ lb, float* __restrict__ out) {
    int gid  = blockIdx.x * blockDim.x + threadIdx.x;
    int n    = gid >> 5;
    if (n >= NN) return;
    int lane = gid & 31;

    int start = d_rowptr[n], end = d_rowptr[n + 1];
    float ad = d_ad2[n];

    float acc = 0.f, den = 0.f;
    for (int base = start; base < end; base += 32) {
        int m   = min(32, end - base);
        int myS = (lane < m) ? __ldg(&d_esrc[base + lane]) : 0;
        float myA = (lane < m) ? __ldg(&d_as2[myS]) : 0.f;
#pragma unroll 4
        for (int i = 0; i < m; i++) {
            int   s  = __shfl_sync(0xffffffffu, myS, i);
            float as = __shfl_sync(0xffffffffu, myA, i);
            float p  = __expf(lrelu(as + ad));
            den += p;
            acc = fmaf(p, d_h2[s * HID + lane], acc);
        }
    }

    float v = eluf(acc / den + b2[lane]);
    float o0 = v * lw[lane * 2 + 0];
    float o1 = v * lw[lane * 2 + 1];
#pragma unroll
    for (int o = 16; o; o >>= 1) {
        o0 += __shfl_xor_sync(0xffffffffu, o0, o);
        o1 += __shfl_xor_sync(0xffffffffu, o1, o);
    }
    if (lane == 0) { out[n * 2 + 0] = o0 + lb[0]; out[n * 2 + 1] = o1 + lb[1]; }
}

// ---------------- launch ----------------
extern "C" void kernel_launch(void* const* d_in, const int* in_sizes, int n_in,
                              void* d_out, int out_size) {
    const float* x        = (const float*)d_in[0];
    const int*   ei       = (const int*)  d_in[1];
    const float* W1       = (const float*)d_in[2];
    const float* att_src1 = (const float*)d_in[3];
    const float* att_dst1 = (const float*)d_in[4];
    const float* b1       = (const float*)d_in[5];
    const float* W2       = (const float*)d_in[6];
    const float* att_src2 = (const float*)d_in[7];
    const float* att_dst2 = (const float*)d_in[8];
    const float* b2       = (const float*)d_in[9];
    const float* lin_w    = (const float*)d_in[10];
    const float* lin_b    = (const float*)d_in[11];
    float* out = (float*)d_out;
    (void)in_sizes; (void)n_in; (void)out_size;

    const int GW = (NN * 32 + 255) / 256;          // warp-per-node blocks

    // CSR build
    k_zero<<<256, 256>>>();
    k_hist<<<(EE + 255) / 256, 256>>>(ei);
    k_scanA<<<SCAN_B, 256>>>();
    k_scanB<<<1, 256>>>();
    k_scanC<<<SCAN_B, 256>>>();
    k_scatter<<<(ET + 255) / 256, 256>>>(ei);

    // layer 1
    k_gemm1<<<(NN + R1 - 1) / R1, 128>>>(x, W1, att_src1, att_dst1);
    k_gather1<<<GW, 256>>>(b1);

    // layer 2
    k_gemm2<<<(NN + 31) / 32, 256>>>(W2, att_src2, att_dst2);
    k_gather2<<<GW, 256>>>(b2, lin_w, lin_b, out);
}

// round 7
// speedup vs baseline: 2.2321x; 1.0479x over previous
#include <cuda_runtime.h>
#include <cuda_fp16.h>
#include <math.h>

#define NN    50000
#define EE    800000
#define ET    (EE + NN)
#define IND   256
#define HID   32
#define HEADS 4
#define HH    (HEADS * HID)      // 128
#define SLOPE 0.2f
#define R1    40                 // rows per block in gemm1 (1250 blocks exactly)

// ---------------- scratch ----------------
__device__ __half d_h1h[NN * HH];   // fp16 copy of h1 for gather
__device__ float d_as1[NN * HEADS];
__device__ float d_ad1[NN * HEADS];
__device__ float d_out1[NN * HH];

__device__ __half d_h2h[NN * HID];  // fp16 h2 for gather
__device__ float d_as2[NN];
__device__ float d_ad2[NN];

// CSR scratch
__device__ int d_cnt   [NN];
__device__ int d_cnt2  [NN];
__device__ int d_rowptr[NN + 1];
__device__ int d_esrc  [ET];
__device__ int d_bsum  [256];
__device__ int d_boff  [256];

#define SCAN_B 196               // ceil(50000/256)

// ---------------- helpers ----------------
__device__ __forceinline__ float lrelu(float v) { return v > 0.0f ? v : SLOPE * v; }
__device__ __forceinline__ float eluf (float v) { return v > 0.0f ? v : __expf(v) - 1.0f; }

__device__ __forceinline__ unsigned long long packf2(float lo, float hi) {
    unsigned long long r;
    asm("mov.b64 %0, {%1, %2};" : "=l"(r) : "f"(lo), "f"(hi));
    return r;
}
__device__ __forceinline__ void fma2(unsigned long long& d, unsigned long long a, unsigned long long b) {
    asm("fma.rn.f32x2 %0, %1, %2, %0;" : "+l"(d) : "l"(a), "l"(b));
}
__device__ __forceinline__ float unpack_sum(unsigned long long v) {
    float lo = __uint_as_float((unsigned int)(v & 0xffffffffull));
    float hi = __uint_as_float((unsigned int)(v >> 32));
    return lo + hi;
}

// ---------------- CSR build ----------------
__global__ void k_hist(const int* __restrict__ ei) {
    int e = blockIdx.x * blockDim.x + threadIdx.x;
    if (e < EE) atomicAdd(&d_cnt[ei[EE + e]], 1);
}

// phase A: per-block scan of 256 counts (+1 self-loop each); local exclusive -> rowptr
__global__ void k_scanA() {
    __shared__ int sh[256];
    int t = threadIdx.x;
    int idx = blockIdx.x * 256 + t;
    int c = (idx < NN) ? (d_cnt[idx] + 1) : 0;   // +1: self loop
    sh[t] = c;
    __syncthreads();
#pragma unroll
    for (int off = 1; off < 256; off <<= 1) {
        int v = (t >= off) ? sh[t - off] : 0;
        __syncthreads();
        sh[t] += v;
        __syncthreads();
    }
    if (idx < NN) d_rowptr[idx] = sh[t] - c;
    if (t == 255) d_bsum[blockIdx.x] = sh[255];
}

__global__ void k_scanB() {
    __shared__ int sh[256];
    int t = threadIdx.x;
    int c = (t < SCAN_B) ? d_bsum[t] : 0;
    sh[t] = c;
    __syncthreads();
#pragma unroll
    for (int off = 1; off < 256; off <<= 1) {
        int v = (t >= off) ? sh[t - off] : 0;
        __syncthreads();
        sh[t] += v;
        __syncthreads();
    }
    if (t < SCAN_B) d_boff[t] = sh[t] - c;
}

__global__ void k_scanC() {
    int idx = blockIdx.x * 256 + threadIdx.x;
    if (idx < NN) d_rowptr[idx] += d_boff[blockIdx.x];
    if (idx == 0) d_rowptr[NN] = ET;
}

__global__ void k_scatter(const int* __restrict__ ei) {
    int id = blockIdx.x * blockDim.x + threadIdx.x;
    if (id >= ET) return;
    int s, d;
    if (id < EE) { s = ei[id]; d = ei[EE + id]; }
    else         { s = id - EE; d = id - EE; }
    int pos = d_rowptr[d] + atomicAdd(&d_cnt2[d], 1);
    d_esrc[pos] = s;
}

// ---------------- layer 1: GEMM (R1 rows/block, f32x2) + attention scalars ----------------
__global__ void __launch_bounds__(128) k_gemm1(
        const float* __restrict__ x, const float* __restrict__ W,
        const float* __restrict__ att_s, const float* __restrict__ att_d) {
    __shared__ float xs[R1 * IND];   // 40 KB
    int n0 = blockIdx.x * R1;
    int j  = threadIdx.x;

    const float4* x4  = (const float4*)(x + (size_t)n0 * IND);
    float4*       xs4 = (float4*)xs;
#pragma unroll
    for (int t = 0; t < R1 * IND / 4 / 128; t++) {
        int idx = j + t * 128;
        xs4[idx] = x4[idx];                       // NN divisible by R1: no tail
    }
    __syncthreads();

    unsigned long long acc[R1];
#pragma unroll
    for (int r = 0; r < R1; r++) acc[r] = 0ull;

#pragma unroll 1
    for (int k = 0; k < IND; k += 4) {
        float w0 = __ldg(&W[(k + 0) * HH + j]);
        float w1 = __ldg(&W[(k + 1) * HH + j]);
        float w2 = __ldg(&W[(k + 2) * HH + j]);
        float w3 = __ldg(&W[(k + 3) * HH + j]);
        unsigned long long w01 = packf2(w0, w1);
        unsigned long long w23 = packf2(w2, w3);
#pragma unroll
        for (int r = 0; r < R1; r++) {
            ulonglong2 xv = *(const ulonglong2*)&xs[r * IND + k];
            fma2(acc[r], xv.x, w01);
            fma2(acc[r], xv.y, w23);
        }
    }

    int lane = j & 31, head = j >> 5;
    float es = att_s[head * HID + lane];
    float ed = att_d[head * HID + lane];

#pragma unroll
    for (int r = 0; r < R1; r++) {
        int n = n0 + r;
        float a = unpack_sum(acc[r]);
        d_h1h[(size_t)n * HH + j] = __float2half_rn(a);
        float s = a * es, t = a * ed;
#pragma unroll
        for (int o = 16; o; o >>= 1) {
            s += __shfl_xor_sync(0xffffffffu, s, o);
            t += __shfl_xor_sync(0xffffffffu, t, o);
        }
        if (lane == 0) { d_as1[n * HEADS + head] = s; d_ad1[n * HEADS + head] = t; }
    }
}

// ---------------- layer 1: CSR gather (fp16 rows, chunked shuffle) ----------------
// one warp per destination node; lane covers cols [lane*4, lane*4+4), head = lane>>3
__global__ void k_gather1(const float* __restrict__ b1) {
    int gid  = blockIdx.x * blockDim.x + threadIdx.x;
    int n    = gid >> 5;
    if (n >= NN) return;
    int lane = gid & 31;
    int h    = lane >> 3;

    int start = d_rowptr[n], end = d_rowptr[n + 1];
    float ad = d_ad1[n * 4 + h];

    float4 acc = make_float4(0.f, 0.f, 0.f, 0.f);
    float  den = 0.f;

    for (int base = start; base < end; base += 32) {
        int m   = min(32, end - base);
        int myS = (lane < m) ? __ldg(&d_esrc[base + lane]) : 0;
#pragma unroll 4
        for (int i = 0; i < m; i++) {
            int s = __shfl_sync(0xffffffffu, myS, i);
            float p = __expf(lrelu(__ldg(&d_as1[s * 4 + h]) + ad));
            uint2 raw = *(const uint2*)&d_h1h[(size_t)s * HH + lane * 4];
            float2 f01 = __half22float2(*(__half2*)&raw.x);
            float2 f23 = __half22float2(*(__half2*)&raw.y);
            den  += p;
            acc.x = fmaf(p, f01.x, acc.x);
            acc.y = fmaf(p, f01.y, acc.y);
            acc.z = fmaf(p, f23.x, acc.z);
            acc.w = fmaf(p, f23.y, acc.w);
        }
    }

    float inv = 1.0f / den;
    float4 bb = *(const float4*)&b1[lane * 4];
    acc.x = eluf(acc.x * inv + bb.x);
    acc.y = eluf(acc.y * inv + bb.y);
    acc.z = eluf(acc.z * inv + bb.z);
    acc.w = eluf(acc.w * inv + bb.w);
    *(float4*)&d_out1[(size_t)n * HH + lane * 4] = acc;
}

// ---------------- layer 2: GEMM (32 nodes/block) + attention scalars ----------------
__global__ void k_gemm2(const float* __restrict__ W2,
                        const float* __restrict__ att_s, const float* __restrict__ att_d) {
    __shared__ float Ws[HH * HID];    // 16 KB
    __shared__ float xs[32][HH];      // 16 KB
    int tid = threadIdx.x;
    for (int t = tid; t < HH * HID; t += 256) Ws[t] = W2[t];
    int w = tid >> 5, lane = tid & 31;
    int n0 = blockIdx.x * 32;
#pragma unroll
    for (int r = 0; r < 4; r++) {
        int row = w * 4 + r;
        int n = n0 + row;
        if (n < NN)
            *(float4*)&xs[row][lane * 4] = *(const float4*)&d_out1[(size_t)n * HH + lane * 4];
    }
    __syncthreads();

    float as_l = att_s[lane], ad_l = att_d[lane];
#pragma unroll
    for (int r = 0; r < 4; r++) {
        int row = w * 4 + r;
        int n = n0 + row;
        if (n >= NN) break;
        float acc = 0.0f;
#pragma unroll 8
        for (int k = 0; k < HH; k += 4) {
            float4 xv = *(const float4*)&xs[row][k];
            acc += xv.x * Ws[(k + 0) * HID + lane];
            acc += xv.y * Ws[(k + 1) * HID + lane];
            acc += xv.z * Ws[(k + 2) * HID + lane];
            acc += xv.w * Ws[(k + 3) * HID + lane];
        }
        d_h2h[n * HID + lane] = __float2half_rn(acc);
        float s = acc * as_l, t = acc * ad_l;
#pragma unroll
        for (int o = 16; o; o >>= 1) {
            s += __shfl_xor_sync(0xffffffffu, s, o);
            t += __shfl_xor_sync(0xffffffffu, t, o);
        }
        if (lane == 0) { d_as2[n] = s; d_ad2[n] = t; }
    }
}

// ---------------- layer 2: CSR gather + bias/ELU + classifier ----------------
__global__ void k_gather2(const float* __restrict__ b2, const float* __restrict__ lw,
                          const float* __restrict__ lb, float* __restrict__ out) {
    int gid  = blockIdx.x * blockDim.x + threadIdx.x;
    int n    = gid >> 5;
    if (n >= NN) return;
    int lane = gid & 31;

    int start = d_rowptr[n], end = d_rowptr[n + 1];
    float ad = d_ad2[n];

    float acc = 0.f, den = 0.f;
    for (int base = start; base < end; base += 32) {
        int m   = min(32, end - base);
        int myS = (lane < m) ? __ldg(&d_esrc[base + lane]) : 0;
        float myA = (lane < m) ? __ldg(&d_as2[myS]) : 0.f;
#pragma unroll 4
        for (int i = 0; i < m; i++) {
            int   s  = __shfl_sync(0xffffffffu, myS, i);
            float as = __shfl_sync(0xffffffffu, myA, i);
            float p  = __expf(lrelu(as + ad));
            den += p;
            acc = fmaf(p, __half2float(d_h2h[s * HID + lane]), acc);
        }
    }

    float v = eluf(acc / den + b2[lane]);
    float o0 = v * lw[lane * 2 + 0];
    float o1 = v * lw[lane * 2 + 1];
#pragma unroll
    for (int o = 16; o; o >>= 1) {
        o0 += __shfl_xor_sync(0xffffffffu, o0, o);
        o1 += __shfl_xor_sync(0xffffffffu, o1, o);
    }
    if (lane == 0) { out[n * 2 + 0] = o0 + lb[0]; out[n * 2 + 1] = o1 + lb[1]; }
}

// ---------------- launch ----------------
extern "C" void kernel_launch(void* const* d_in, const int* in_sizes, int n_in,
                              void* d_out, int out_size) {
    const float* x        = (const float*)d_in[0];
    const int*   ei       = (const int*)  d_in[1];
    const float* W1       = (const float*)d_in[2];
    const float* att_src1 = (const float*)d_in[3];
    const float* att_dst1 = (const float*)d_in[4];
    const float* b1       = (const float*)d_in[5];
    const float* W2       = (const float*)d_in[6];
    const float* att_src2 = (const float*)d_in[7];
    const float* att_dst2 = (const float*)d_in[8];
    const float* b2       = (const float*)d_in[9];
    const float* lin_w    = (const float*)d_in[10];
    const float* lin_b    = (const float*)d_in[11];
    float* out = (float*)d_out;
    (void)in_sizes; (void)n_in; (void)out_size;

    const int GW = (NN * 32 + 255) / 256;

    // CSR build (counters zeroed via capturable async memsets)
    void* cntp = nullptr; void* cnt2p = nullptr;
    cudaGetSymbolAddress(&cntp,  d_cnt);
    cudaGetSymbolAddress(&cnt2p, d_cnt2);
    cudaMemsetAsync(cntp,  0, NN * sizeof(int), 0);
    cudaMemsetAsync(cnt2p, 0, NN * sizeof(int), 0);
    k_hist<<<(EE + 255) / 256, 256>>>(ei);
    k_scanA<<<SCAN_B, 256>>>();
    k_scanB<<<1, 256>>>();
    k_scanC<<<SCAN_B, 256>>>();
    k_scatter<<<(ET + 255) / 256, 256>>>(ei);

    // layer 1
    k_gemm1<<<NN / R1, 128>>>(x, W1, att_src1, att_dst1);
    k_gather1<<<GW, 256>>>(b1);

    // layer 2
    k_gemm2<<<(NN + 31) / 32, 256>>>(W2, att_src2, att_dst2);
    k_gather2<<<GW, 256>>>(b2, lin_w, lin_b, out);
}

// round 8
// speedup vs baseline: 2.6242x; 1.1757x over previous
#include <cuda_runtime.h>
#include <cuda_fp16.h>
#include <mma.h>
#include <math.h>

using namespace nvcuda;

#define NN    50000
#define EE    800000
#define ET    (EE + NN)
#define IND   256
#define HID   32
#define HEADS 4
#define HH    (HEADS * HID)      // 128
#define SLOPE 0.2f

// gemm1 tiling
#define BM    128
#define BK    32
#define XSTR  (BK + 4)           // 36 (float4-aligned: 144B)
#define WSTR  (HH + 4)           // 132 (528B, 16B-aligned)
#define OSTR  (HH + 4)           // 132
#define GEMM1_SMEM (BM * OSTR * 4)   // 67584 B (output reuse dominates)

// ---------------- scratch ----------------
__device__ __half d_h1h[NN * HH];   // fp16 h1 for gather
__device__ float d_as1[NN * HEADS];
__device__ float d_ad1[NN * HEADS];
__device__ float d_out1[NN * HH];

__device__ __half d_h2h[NN * HID];  // fp16 h2 for gather
__device__ float d_as2[NN];
__device__ float d_ad2[NN];

// CSR scratch
__device__ int d_cnt   [NN];
__device__ int d_cnt2  [NN];
__device__ int d_rowptr[NN + 1];
__device__ int d_esrc  [ET];
__device__ int d_bsum  [256];
__device__ int d_boff  [256];

#define SCAN_B 196               // ceil(50000/256)

// ---------------- helpers ----------------
__device__ __forceinline__ float lrelu(float v) { return v > 0.0f ? v : SLOPE * v; }
__device__ __forceinline__ float eluf (float v) { return v > 0.0f ? v : __expf(v) - 1.0f; }

// ---------------- CSR build ----------------
__global__ void k_hist(const int* __restrict__ ei) {
    int e = blockIdx.x * blockDim.x + threadIdx.x;
    if (e < EE) atomicAdd(&d_cnt[ei[EE + e]], 1);
}

__global__ void k_scanA() {
    __shared__ int sh[256];
    int t = threadIdx.x;
    int idx = blockIdx.x * 256 + t;
    int c = (idx < NN) ? (d_cnt[idx] + 1) : 0;   // +1: self loop
    sh[t] = c;
    __syncthreads();
#pragma unroll
    for (int off = 1; off < 256; off <<= 1) {
        int v = (t >= off) ? sh[t - off] : 0;
        __syncthreads();
        sh[t] += v;
        __syncthreads();
    }
    if (idx < NN) d_rowptr[idx] = sh[t] - c;
    if (t == 255) d_bsum[blockIdx.x] = sh[255];
}

__global__ void k_scanB() {
    __shared__ int sh[256];
    int t = threadIdx.x;
    int c = (t < SCAN_B) ? d_bsum[t] : 0;
    sh[t] = c;
    __syncthreads();
#pragma unroll
    for (int off = 1; off < 256; off <<= 1) {
        int v = (t >= off) ? sh[t - off] : 0;
        __syncthreads();
        sh[t] += v;
        __syncthreads();
    }
    if (t < SCAN_B) d_boff[t] = sh[t] - c;
}

__global__ void k_scanC() {
    int idx = blockIdx.x * 256 + threadIdx.x;
    if (idx < NN) d_rowptr[idx] += d_boff[blockIdx.x];
    if (idx == 0) d_rowptr[NN] = ET;
}

__global__ void k_scatter(const int* __restrict__ ei) {
    int id = blockIdx.x * blockDim.x + threadIdx.x;
    if (id >= ET) return;
    int s, d;
    if (id < EE) { s = ei[id]; d = ei[EE + id]; }
    else         { s = id - EE; d = id - EE; }
    int pos = d_rowptr[d] + atomicAdd(&d_cnt2[d], 1);
    d_esrc[pos] = s;
}

// ---------------- layer 1: TF32 tensor-core GEMM + attention scalars ----------------
// 256 threads = 8 warps; warp grid 4(M) x 2(N); warp tile 32x64 = 2x4 m16n16k8 frags
__global__ void __launch_bounds__(256) k_gemm1(
        const float* __restrict__ x, const float* __restrict__ W,
        const float* __restrict__ att_s, const float* __restrict__ att_d) {
    extern __shared__ float smem[];
    float* xs = smem;                    // [BM][XSTR]
    float* ws = smem + BM * XSTR;        // [BK][WSTR]
    float* os = smem;                    // reused after mainloop: [BM][OSTR]

    int tid  = threadIdx.x;
    int wid  = tid >> 5, lane = tid & 31;
    int n0   = blockIdx.x * BM;
    int wm   = wid & 3;                  // row group: wm*32
    int wn   = wid >> 2;                 // col group: wn*64

    wmma::fragment<wmma::accumulator, 16, 16, 8, float> c[2][4];
#pragma unroll
    for (int i = 0; i < 2; i++)
#pragma unroll
        for (int j = 0; j < 4; j++) wmma::fill_fragment(c[i][j], 0.0f);

    for (int k0 = 0; k0 < IND; k0 += BK) {
        // x tile: 128 rows x 32 cols = 1024 float4
#pragma unroll
        for (int it = 0; it < 4; it++) {
            int i   = tid + it * 256;
            int row = i >> 3, kq = i & 7;
            int n   = n0 + row;
            float4 v = make_float4(0.f, 0.f, 0.f, 0.f);
            if (n < NN) v = *(const float4*)&x[(size_t)n * IND + k0 + kq * 4];
            v.x = wmma::__float_to_tf32(v.x);
            v.y = wmma::__float_to_tf32(v.y);
            v.z = wmma::__float_to_tf32(v.z);
            v.w = wmma::__float_to_tf32(v.w);
            *(float4*)&xs[row * XSTR + kq * 4] = v;
        }
        // W tile: 32 rows x 128 cols = 1024 float4
#pragma unroll
        for (int it = 0; it < 4; it++) {
            int i  = tid + it * 256;
            int k  = i >> 5, nq = i & 31;
            float4 v = *(const float4*)&W[(size_t)(k0 + k) * HH + nq * 4];
            v.x = wmma::__float_to_tf32(v.x);
            v.y = wmma::__float_to_tf32(v.y);
            v.z = wmma::__float_to_tf32(v.z);
            v.w = wmma::__float_to_tf32(v.w);
            *(float4*)&ws[k * WSTR + nq * 4] = v;
        }
        __syncthreads();

#pragma unroll
        for (int kk = 0; kk < BK; kk += 8) {
            wmma::fragment<wmma::matrix_a, 16, 16, 8, wmma::precision::tf32, wmma::row_major> a[2];
            wmma::fragment<wmma::matrix_b, 16, 16, 8, wmma::precision::tf32, wmma::row_major> b[4];
#pragma unroll
            for (int i = 0; i < 2; i++)
                wmma::load_matrix_sync(a[i], &xs[(wm * 32 + i * 16) * XSTR + kk], XSTR);
#pragma unroll
            for (int j = 0; j < 4; j++)
                wmma::load_matrix_sync(b[j], &ws[kk * WSTR + wn * 64 + j * 16], WSTR);
#pragma unroll
            for (int i = 0; i < 2; i++)
#pragma unroll
                for (int j = 0; j < 4; j++)
                    wmma::mma_sync(c[i][j], a[i], b[j], c[i][j]);
        }
        __syncthreads();
    }

    // store accumulators to smem (xs/ws regions dead now)
#pragma unroll
    for (int i = 0; i < 2; i++)
#pragma unroll
        for (int j = 0; j < 4; j++)
            wmma::store_matrix_sync(&os[(wm * 32 + i * 16) * OSTR + wn * 64 + j * 16],
                                    c[i][j], OSTR, wmma::mem_row_major);
    __syncthreads();

    // epilogue: fp16 h1 write + attention scalars
    int head = wid & 3;
    int rofs = wid >> 2;
    float es = att_s[head * HID + lane];
    float ed = att_d[head * HID + lane];
#pragma unroll 4
    for (int r2 = 0; r2 < BM; r2 += 2) {
        int r = r2 + rofs;
        int n = n0 + r;
        if (n >= NN) continue;
        float v = os[r * OSTR + head * 32 + lane];
        d_h1h[(size_t)n * HH + head * 32 + lane] = __float2half_rn(v);
        float s = v * es, t = v * ed;
#pragma unroll
        for (int o = 16; o; o >>= 1) {
            s += __shfl_xor_sync(0xffffffffu, s, o);
            t += __shfl_xor_sync(0xffffffffu, t, o);
        }
        if (lane == 0) { d_as1[n * HEADS + head] = s; d_ad1[n * HEADS + head] = t; }
    }
}

// ---------------- layer 1: CSR gather (fp16 rows, chunked shuffle) ----------------
__global__ void k_gather1(const float* __restrict__ b1) {
    int gid  = blockIdx.x * blockDim.x + threadIdx.x;
    int n    = gid >> 5;
    if (n >= NN) return;
    int lane = gid & 31;
    int h    = lane >> 3;

    int start = d_rowptr[n], end = d_rowptr[n + 1];
    float ad = d_ad1[n * 4 + h];

    float4 acc = make_float4(0.f, 0.f, 0.f, 0.f);
    float  den = 0.f;

    for (int base = start; base < end; base += 32) {
        int m   = min(32, end - base);
        int myS = (lane < m) ? __ldg(&d_esrc[base + lane]) : 0;
#pragma unroll 4
        for (int i = 0; i < m; i++) {
            int s = __shfl_sync(0xffffffffu, myS, i);
            float p = __expf(lrelu(__ldg(&d_as1[s * 4 + h]) + ad));
            uint2 raw = *(const uint2*)&d_h1h[(size_t)s * HH + lane * 4];
            float2 f01 = __half22float2(*(__half2*)&raw.x);
            float2 f23 = __half22float2(*(__half2*)&raw.y);
            den  += p;
            acc.x = fmaf(p, f01.x, acc.x);
            acc.y = fmaf(p, f01.y, acc.y);
            acc.z = fmaf(p, f23.x, acc.z);
            acc.w = fmaf(p, f23.y, acc.w);
        }
    }

    float inv = 1.0f / den;
    float4 bb = *(const float4*)&b1[lane * 4];
    acc.x = eluf(acc.x * inv + bb.x);
    acc.y = eluf(acc.y * inv + bb.y);
    acc.z = eluf(acc.z * inv + bb.z);
    acc.w = eluf(acc.w * inv + bb.w);
    *(float4*)&d_out1[(size_t)n * HH + lane * 4] = acc;
}

// ---------------- layer 2: GEMM (32 nodes/block) + attention scalars ----------------
__global__ void k_gemm2(const float* __restrict__ W2,
                        const float* __restrict__ att_s, const float* __restrict__ att_d) {
    __shared__ float Ws[HH * HID];    // 16 KB
    __shared__ float xs[32][HH];      // 16 KB
    int tid = threadIdx.x;
    for (int t = tid; t < HH * HID; t += 256) Ws[t] = W2[t];
    int w = tid >> 5, lane = tid & 31;
    int n0 = blockIdx.x * 32;
#pragma unroll
    for (int r = 0; r < 4; r++) {
        int row = w * 4 + r;
        int n = n0 + row;
        if (n < NN)
            *(float4*)&xs[row][lane * 4] = *(const float4*)&d_out1[(size_t)n * HH + lane * 4];
    }
    __syncthreads();

    float as_l = att_s[lane], ad_l = att_d[lane];
#pragma unroll
    for (int r = 0; r < 4; r++) {
        int row = w * 4 + r;
        int n = n0 + row;
        if (n >= NN) break;
        float acc = 0.0f;
#pragma unroll 8
        for (int k = 0; k < HH; k += 4) {
            float4 xv = *(const float4*)&xs[row][k];
            acc += xv.x * Ws[(k + 0) * HID + lane];
            acc += xv.y * Ws[(k + 1) * HID + lane];
            acc += xv.z * Ws[(k + 2) * HID + lane];
            acc += xv.w * Ws[(k + 3) * HID + lane];
        }
        d_h2h[n * HID + lane] = __float2half_rn(acc);
        float s = acc * as_l, t = acc * ad_l;
#pragma unroll
        for (int o = 16; o; o >>= 1) {
            s += __shfl_xor_sync(0xffffffffu, s, o);
            t += __shfl_xor_sync(0xffffffffu, t, o);
        }
        if (lane == 0) { d_as2[n] = s; d_ad2[n] = t; }
    }
}

// ---------------- layer 2: CSR gather + bias/ELU + classifier ----------------
__global__ void k_gather2(const float* __restrict__ b2, const float* __restrict__ lw,
                          const float* __restrict__ lb, float* __restrict__ out) {
    int gid  = blockIdx.x * blockDim.x + threadIdx.x;
    int n    = gid >> 5;
    if (n >= NN) return;
    int lane = gid & 31;

    int start = d_rowptr[n], end = d_rowptr[n + 1];
    float ad = d_ad2[n];

    float acc = 0.f, den = 0.f;
    for (int base = start; base < end; base += 32) {
        int m   = min(32, end - base);
        int myS = (lane < m) ? __ldg(&d_esrc[base + lane]) : 0;
        float myA = (lane < m) ? __ldg(&d_as2[myS]) : 0.f;
#pragma unroll 4
        for (int i = 0; i < m; i++) {
            int   s  = __shfl_sync(0xffffffffu, myS, i);
            float as = __shfl_sync(0xffffffffu, myA, i);
            float p  = __expf(lrelu(as + ad));
            den += p;
            acc = fmaf(p, __half2float(d_h2h[s * HID + lane]), acc);
        }
    }

    float v = eluf(acc / den + b2[lane]);
    float o0 = v * lw[lane * 2 + 0];
    float o1 = v * lw[lane * 2 + 1];
#pragma unroll
    for (int o = 16; o; o >>= 1) {
        o0 += __shfl_xor_sync(0xffffffffu, o0, o);
        o1 += __shfl_xor_sync(0xffffffffu, o1, o);
    }
    if (lane == 0) { out[n * 2 + 0] = o0 + lb[0]; out[n * 2 + 1] = o1 + lb[1]; }
}

// ---------------- launch ----------------
extern "C" void kernel_launch(void* const* d_in, const int* in_sizes, int n_in,
                              void* d_out, int out_size) {
    const float* x        = (const float*)d_in[0];
    const int*   ei       = (const int*)  d_in[1];
    const float* W1       = (const float*)d_in[2];
    const float* att_src1 = (const float*)d_in[3];
    const float* att_dst1 = (const float*)d_in[4];
    const float* b1       = (const float*)d_in[5];
    const float* W2       = (const float*)d_in[6];
    const float* att_src2 = (const float*)d_in[7];
    const float* att_dst2 = (const float*)d_in[8];
    const float* b2       = (const float*)d_in[9];
    const float* lin_w    = (const float*)d_in[10];
    const float* lin_b    = (const float*)d_in[11];
    float* out = (float*)d_out;
    (void)in_sizes; (void)n_in; (void)out_size;

    const int GW = (NN * 32 + 255) / 256;

    static bool attr_set = false;
    if (!attr_set) {
        cudaFuncSetAttribute(k_gemm1, cudaFuncAttributeMaxDynamicSharedMemorySize, GEMM1_SMEM);
        attr_set = true;
    }

    // CSR build (counters zeroed via capturable async memsets)
    void* cntp = nullptr; void* cnt2p = nullptr;
    cudaGetSymbolAddress(&cntp,  d_cnt);
    cudaGetSymbolAddress(&cnt2p, d_cnt2);
    cudaMemsetAsync(cntp,  0, NN * sizeof(int), 0);
    cudaMemsetAsync(cnt2p, 0, NN * sizeof(int), 0);
    k_hist<<<(EE + 255) / 256, 256>>>(ei);
    k_scanA<<<SCAN_B, 256>>>();
    k_scanB<<<1, 256>>>();
    k_scanC<<<SCAN_B, 256>>>();
    k_scatter<<<(ET + 255) / 256, 256>>>(ei);

    // layer 1
    k_gemm1<<<(NN + BM - 1) / BM, 256, GEMM1_SMEM>>>(x, W1, att_src1, att_dst1);
    k_gather1<<<GW, 256>>>(b1);

    // layer 2
    k_gemm2<<<(NN + 31) / 32, 256>>>(W2, att_src2, att_dst2);
    k_gather2<<<GW, 256>>>(b2, lin_w, lin_b, out);
}